// round 11
// baseline (speedup 1.0000x reference)
#include <cuda_runtime.h>
#include <cuda_bf16.h>

#define VOCAB 50000
#define D 256
#define E 20000
#define L 20

// ---------------- scratch (static device globals; no allocation) ----------------
__device__ float g_qemb[D];
__device__ float g_g0[D];        // alpha(d) * qemb[d]
__device__ float g_g1[D];        // beta(d)  * qemb[d]
__device__ float g_u[VOCAB];
__device__ float g_w[VOCAB];
__device__ __align__(16) float g_A[VOCAB];  // unnormalized attention mass per vocab id
__device__ __align__(16) float g_B[VOCAB];  // same, weighted by l/L
__device__ float g_accA[D];
__device__ float g_accB[D];
__device__ float g_wte1[D];
__device__ float g_sumw;         // sum of exp(scores)
__device__ float g_sumexp;       // sum of exp(logits)

__device__ __forceinline__ float warp_sum(float v) {
    #pragma unroll
    for (int o = 16; o > 0; o >>= 1) v += __shfl_xor_sync(0xffffffffu, v, o);
    return v;
}

__device__ __forceinline__ float dot8(float4 x0, float4 x1, float4 c0, float4 c1) {
    return x0.x*c0.x + x0.y*c0.y + x0.z*c0.z + x0.w*c0.w
         + x1.x*c1.x + x1.y*c1.y + x1.z*c1.z + x1.w*c1.w;
}

// Forced-order loads: asm volatile cannot be reordered/sunk by ptxas, so a
// batch of these issues back-to-back in SASS -> real MLP.
__device__ __forceinline__ float4 ldg128v(const float4* p) {
    float4 v;
    asm volatile("ld.global.nc.v4.f32 {%0,%1,%2,%3}, [%4];"
                 : "=f"(v.x), "=f"(v.y), "=f"(v.z), "=f"(v.w) : "l"(p));
    return v;
}
__device__ __forceinline__ float ldg32v(const float* p) {
    float v;
    asm volatile("ld.global.nc.f32 %0, [%1];" : "=f"(v) : "l"(p));
    return v;
}

// ---------------- K1: q_emb + derived vectors, zero accumulators ----------------
__global__ void k1_qemb(const int* __restrict__ question,
                        const float* __restrict__ q_table) {
    int d = threadIdx.x;                         // 256 threads
    float a  = 1.0f - (float)d * (1.0f / D);
    float be = 2.0f * (float)d * (1.0f / D) - 1.0f;
    float s = 0.0f;
    #pragma unroll
    for (int l = 0; l < L; ++l) {
        int v = question[l];
        float pe = a + ((float)l * (1.0f / L)) * be;
        s += __ldg(&q_table[(size_t)v * D + d]) * pe;
    }
    g_qemb[d] = s;
    g_g0[d] = a * s;
    g_g1[d] = be * s;
    g_accA[d] = 0.0f; g_accB[d] = 0.0f; g_wte1[d] = 0.0f;
    if (d == 0) { g_sumw = 0.0f; g_sumexp = 0.0f; }
}

// ---------------- K2: u[v], w[v] over q_table; zero A/B --------------------------
// 2 rows per warp, 16 rows/block, grid 3125. 4 forced-batch LDG.128 per thread.
__global__ void k2_uw(const float* __restrict__ q_table) {
    __shared__ float4 s0[64], s1[64];
    int t = threadIdx.x;                      // 256
    if (t < 64) {
        s0[t] = ((const float4*)g_g0)[t];
        s1[t] = ((const float4*)g_g1)[t];
    }
    __syncthreads();
    int warp = t >> 5, lane = t & 31;
    int vbase = blockIdx.x * 16 + warp * 2;
    const float4* rowA = (const float4*)(q_table + (size_t)vbase * D);
    const float4* rowB = (const float4*)(q_table + (size_t)(vbase + 1) * D);
    float4 xa0 = ldg128v(&rowA[lane]);
    float4 xa1 = ldg128v(&rowA[lane + 32]);
    float4 xb0 = ldg128v(&rowB[lane]);
    float4 xb1 = ldg128v(&rowB[lane + 32]);
    float4 c0 = s0[lane], c1 = s0[lane + 32];
    float4 d0 = s1[lane], d1 = s1[lane + 32];
    float u0 = dot8(xa0, xa1, c0, c1);
    float w0 = dot8(xa0, xa1, d0, d1);
    float u1 = dot8(xb0, xb1, c0, c1);
    float w1 = dot8(xb0, xb1, d0, d1);
    u0 = warp_sum(u0); w0 = warp_sum(w0);
    u1 = warp_sum(u1); w1 = warp_sum(w1);
    if (lane == 0) {
        g_u[vbase] = u0;     g_w[vbase] = w0;
        g_u[vbase + 1] = u1; g_w[vbase + 1] = w1;
    }
    if (t < 16) { g_A[blockIdx.x * 16 + t] = 0.0f; g_B[blockIdx.x * 16 + t] = 0.0f; }
}

// ---------------- K34: fused scores + exp + A/B scatter + weights@te1 ------------
#define K34_CHUNK  32
#define K34_BLOCKS (E / K34_CHUNK)    // 625
__global__ void k34_weights(const int* __restrict__ evidence,
                            const float* __restrict__ te2,
                            const float* __restrict__ te1) {
    __shared__ float4 sq[64];
    __shared__ float s_w[K34_CHUNK];
    int t = threadIdx.x;                      // 256
    int warp = t >> 5, lane = t & 31;
    if (t < 64) sq[t] = ((const float4*)g_qemb)[t];
    __syncthreads();
    int e0 = blockIdx.x * K34_CHUNK;
    float4 q0 = sq[lane], q1 = sq[lane + 32];
    // batch all 8 te2 float4 loads up front (forced order)
    float4 x0[4], x1[4];
    #pragma unroll
    for (int r = 0; r < 4; ++r) {
        const float4* row = (const float4*)(te2 + (size_t)(e0 + warp * 4 + r) * D);
        x0[r] = ldg128v(&row[lane]);
        x1[r] = ldg128v(&row[lane + 32]);
    }
    float part[4];
    #pragma unroll
    for (int r = 0; r < 4; ++r) {
        int e = e0 + warp * 4 + r;
        float p = 0.0f;
        if (lane < L) {
            int v = __ldg(&evidence[e * L + lane]);
            p = g_u[v] + ((float)lane * (1.0f / L)) * g_w[v];
        }
        part[r] = p + dot8(x0[r], x1[r], q0, q1);
    }
    #pragma unroll
    for (int r = 0; r < 4; ++r) part[r] = warp_sum(part[r]);
    if (lane == 0) {
        #pragma unroll
        for (int r = 0; r < 4; ++r) s_w[warp * 4 + r] = part[r];
    }
    __syncthreads();
    if (t < 32) {
        float w = expf(s_w[t]);
        s_w[t] = w;
        float s = warp_sum(w);
        if (t == 0) atomicAdd(&g_sumw, s);
    }
    __syncthreads();
    for (int i = t; i < K34_CHUNK * L; i += 256) {
        int el = i / L;
        int l  = i - el * L;
        int v  = __ldg(&evidence[(e0 + el) * L + l]);
        float w = s_w[el];
        atomicAdd(&g_A[v], w);
        atomicAdd(&g_B[v], w * ((float)l * (1.0f / L)));
    }
    // wte1: 4 groups of 8 forced-batch scalar loads
    int d = t;
    float acc = 0.0f;
    #pragma unroll
    for (int g = 0; g < 4; ++g) {
        float x[8];
        #pragma unroll
        for (int k = 0; k < 8; ++k)
            x[k] = ldg32v(&te1[(size_t)(e0 + g * 8 + k) * D + d]);
        #pragma unroll
        for (int k = 0; k < 8; ++k)
            acc += s_w[g * 8 + k] * x[k];
    }
    atomicAdd(&g_wte1[d], acc);
}

// ---------------- K5: accA/accB = A@e_table, B@e_table ---------------------------
// Contiguous 16-row (16KB) chunks, 3125 chunks total. Thread t owns float4
// column col4 = t&63 and row-group r0 = t>>6; per chunk it loads 4 forced-batch
// LDG.128 covering rows r0+4k. Row-group reduction in smem, then atomics.
#define K5_GRID 1184
__global__ void k5_etable(const float* __restrict__ e_table) {
    __shared__ float4 s_a[4][64];
    __shared__ float4 s_b[4][64];
    int t = threadIdx.x;                      // 256
    int col4 = t & 63, r0 = t >> 6;
    const int nchunks = VOCAB / 16;           // 3125 (exact)
    float4 a = make_float4(0.f, 0.f, 0.f, 0.f);
    float4 b = make_float4(0.f, 0.f, 0.f, 0.f);
    for (int c = blockIdx.x; c < nchunks; c += K5_GRID) {
        int v0 = c * 16;
        const float4* src = (const float4*)e_table + (size_t)v0 * 64;
        float Ac[4], Bc[4];
        #pragma unroll
        for (int k = 0; k < 4; ++k) {
            Ac[k] = ldg32v(&g_A[v0 + r0 + 4 * k]);
            Bc[k] = ldg32v(&g_B[v0 + r0 + 4 * k]);
        }
        float4 x[4];
        #pragma unroll
        for (int k = 0; k < 4; ++k)
            x[k] = ldg128v(src + t + k * 256);   // row r0+4k, col col4
        #pragma unroll
        for (int k = 0; k < 4; ++k) {
            a.x += Ac[k] * x[k].x; a.y += Ac[k] * x[k].y;
            a.z += Ac[k] * x[k].z; a.w += Ac[k] * x[k].w;
            b.x += Bc[k] * x[k].x; b.y += Bc[k] * x[k].y;
            b.z += Bc[k] * x[k].z; b.w += Bc[k] * x[k].w;
        }
    }
    s_a[r0][col4] = a; s_b[r0][col4] = b;
    __syncthreads();
    if (r0 == 0) {
        float4 a1 = s_a[1][col4], a2 = s_a[2][col4], a3 = s_a[3][col4];
        float4 b1 = s_b[1][col4], b2 = s_b[2][col4], b3 = s_b[3][col4];
        a.x += a1.x + a2.x + a3.x; a.y += a1.y + a2.y + a3.y;
        a.z += a1.z + a2.z + a3.z; a.w += a1.w + a2.w + a3.w;
        b.x += b1.x + b2.x + b3.x; b.y += b1.y + b2.y + b3.y;
        b.z += b1.z + b2.z + b3.z; b.w += b1.w + b2.w + b3.w;
        int d = col4 * 4;
        atomicAdd(&g_accA[d + 0], a.x); atomicAdd(&g_accA[d + 1], a.y);
        atomicAdd(&g_accA[d + 2], a.z); atomicAdd(&g_accA[d + 3], a.w);
        atomicAdd(&g_accB[d + 0], b.x); atomicAdd(&g_accB[d + 1], b.y);
        atomicAdd(&g_accB[d + 2], b.z); atomicAdd(&g_accB[d + 3], b.w);
    }
}

// ---------------- K6: logits + exp + block-aggregated sumexp ---------------------
// 2 rows per warp, 16 rows/block, grid 3125. Forced-batch LDG.128 on W.
__global__ void k6_logits(const float* __restrict__ W, const float* __restrict__ b,
                          float* __restrict__ out) {
    __shared__ float s_feat[D];
    __shared__ float s_p[8];
    int t = threadIdx.x;                      // 256
    {
        float a  = 1.0f - (float)t * (1.0f / D);
        float be = 2.0f * (float)t * (1.0f / D) - 1.0f;
        float invS = 1.0f / g_sumw;
        s_feat[t] = (a * g_accA[t] + be * g_accB[t] + g_wte1[t]) * invS + g_qemb[t];
    }
    __syncthreads();
    int warp = t >> 5, lane = t & 31;
    int vbase = blockIdx.x * 16 + warp * 2;
    const float4* rowA = (const float4*)(W + (size_t)vbase * D);
    const float4* rowB = (const float4*)(W + (size_t)(vbase + 1) * D);
    float4 xa0 = ldg128v(&rowA[lane]);
    float4 xa1 = ldg128v(&rowA[lane + 32]);
    float4 xb0 = ldg128v(&rowB[lane]);
    float4 xb1 = ldg128v(&rowB[lane + 32]);
    const float4* sf = (const float4*)s_feat;
    float4 f0 = sf[lane], f1 = sf[lane + 32];
    float s0 = dot8(xa0, xa1, f0, f1);
    float s1 = dot8(xb0, xb1, f0, f1);
    s0 = warp_sum(s0); s1 = warp_sum(s1);
    float p_sum = 0.0f;
    if (lane == 0) {
        float p0 = expf(s0 + __ldg(&b[vbase]));
        float p1 = expf(s1 + __ldg(&b[vbase + 1]));
        out[vbase] = p0;                      // unnormalized
        out[vbase + 1] = p1;
        p_sum = p0 + p1;
        s_p[warp] = p_sum;
    }
    __syncthreads();
    if (t < 8) {
        float x = s_p[t];
        #pragma unroll
        for (int o = 4; o > 0; o >>= 1) x += __shfl_xor_sync(0xffu, x, o);
        if (t == 0) atomicAdd(&g_sumexp, x);
    }
}

// ---------------- K7: normalize output -------------------------------------------
__global__ void k7_scale(float* __restrict__ out) {
    int i = blockIdx.x * blockDim.x + threadIdx.x;
    float inv = 1.0f / g_sumexp;
    if (i < VOCAB) out[i] *= inv;
}

// ---------------- launch ---------------------------------------------------------
extern "C" void kernel_launch(void* const* d_in, const int* in_sizes, int n_in,
                              void* d_out, int out_size) {
    const int*   evidence = (const int*)  d_in[0];
    const int*   question = (const int*)  d_in[1];
    const float* q_table  = (const float*)d_in[2];
    const float* e_table  = (const float*)d_in[3];
    const float* te1      = (const float*)d_in[4];
    const float* te2      = (const float*)d_in[5];
    const float* W        = (const float*)d_in[6];
    const float* b        = (const float*)d_in[7];
    float* out = (float*)d_out;

    k1_qemb<<<1, 256>>>(question, q_table);
    k2_uw<<<VOCAB / 16, 256>>>(q_table);
    k34_weights<<<K34_BLOCKS, 256>>>(evidence, te2, te1);
    k5_etable<<<K5_GRID, 256>>>(e_table);
    k6_logits<<<VOCAB / 16, 256>>>(W, b, out);
    k7_scale<<<(VOCAB + 255) / 256, 256>>>(out);
}